// round 4
// baseline (speedup 1.0000x reference)
#include <cuda_runtime.h>
#include <cuda_bf16.h>
#include <cstdint>

// LongformerAttention_44315472560501
// output            = hidden_states  (identity copy, 32 MiB f32)
// attention_weights = zeros          (128 MiB f32)
//
// R4: single fused streaming kernel, ONE launch.
//  - contiguous per-block chunks (DRAM page locality, clean 128B coalescing)
//  - __ldcs / __stcs streaming hints: 192 MiB written once, never re-read by
//    this kernel -> evict-first keeps L2 dirty-line churn down
//  - scalar tail folded into the last block (no second launch)
// R1 measured 224 MiB in 33.3us = 7.05 TB/s aggregate (88% of spec); this
// round targets the last few percent + launch overhead.

__global__ void fused_copy_zero(const float4* __restrict__ src,
                                float4* __restrict__ dst,
                                long long n_copy4,
                                long long n_total4,
                                long long chunk4,      // float4s per block (mult of blockDim)
                                const float* __restrict__ src_s,
                                float* __restrict__ dst_s,
                                long long n_copy,
                                long long n_total)
{
    const int tx = threadIdx.x;
    const int bd = blockDim.x;

    long long start = (long long)blockIdx.x * chunk4;
    long long end   = start + chunk4;
    if (end > n_total4) end = n_total4;

    const float4 z = make_float4(0.f, 0.f, 0.f, 0.f);

    for (long long i = start + tx; i < end; i += bd) {
        if (i < n_copy4) {
            __stcs(&dst[i], __ldcs(&src[i]));
        } else {
            __stcs(&dst[i], z);
        }
    }

    // scalar tail (floats beyond the last full float4), last block only
    if (blockIdx.x == gridDim.x - 1) {
        long long t0 = n_total4 * 4;
        for (long long i = t0 + tx; i < n_total; i += bd) {
            dst_s[i] = (i < n_copy) ? src_s[i] : 0.f;
        }
    }
}

extern "C" void kernel_launch(void* const* d_in, const int* in_sizes, int n_in,
                              void* d_out, int out_size)
{
    const float* hidden = (const float*)d_in[0];
    float* out = (float*)d_out;

    long long n_total = (long long)out_size;
    long long n_copy  = (long long)in_sizes[0];
    if (n_copy > n_total) n_copy = n_total;

    long long n_total4 = n_total / 4;
    long long n_copy4  = n_copy  / 4;

    const int threads = 256;
    int blocks = 148 * 16;   // R1's best-measured geometry (2368 blocks)

    // contiguous chunk per block, rounded up to a multiple of blockDim so
    // every warp's 128B segment stays aligned
    long long chunk4 = (n_total4 + blocks - 1) / blocks;
    chunk4 = ((chunk4 + threads - 1) / threads) * threads;
    if (chunk4 < threads) chunk4 = threads;
    // shrink grid if rounding left trailing empty blocks
    long long needed = (n_total4 + chunk4 - 1) / chunk4;
    if (needed < 1) needed = 1;
    if ((long long)blocks > needed) blocks = (int)needed;

    fused_copy_zero<<<blocks, threads>>>(
        (const float4*)hidden, (float4*)out,
        n_copy4, n_total4, chunk4,
        hidden, out, n_copy, n_total);
}

// round 5
// speedup vs baseline: 1.1765x; 1.1765x over previous
#include <cuda_runtime.h>
#include <cuda_bf16.h>
#include <cstdint>

// LongformerAttention_44315472560501
// output            = hidden_states  (identity copy, 32 MiB f32)
// attention_weights = zeros          (128 MiB f32)
//
// R5: parallel-branch graph. Fork the D2D memcpy onto a secondary stream
// (captured via event fork/join) so it overlaps the big memsetAsync instead
// of serializing. Four hand-written kernel variants all pinned at ~34us
// (DRAM ceiling for this 33.5MB-read / 201MB-write mix); the remaining
// lever is engine-level concurrency (CE copy || SM memset).
//
// No device memory is allocated: only a stream + 2 events, created once on
// the first (non-captured) correctness call. Falls back to the proven serial
// R3 path if creation fails.

static cudaStream_t g_side = nullptr;
static cudaEvent_t  g_fork = nullptr;
static cudaEvent_t  g_join = nullptr;
static int          g_ready = 0;   // 0=uninit, 1=ok, -1=failed

extern "C" void kernel_launch(void* const* d_in, const int* in_sizes, int n_in,
                              void* d_out, int out_size)
{
    const float* hidden = (const float*)d_in[0];
    float* out = (float*)d_out;

    long long n_total = (long long)out_size;
    long long n_copy  = (long long)in_sizes[0];
    if (n_copy > n_total) n_copy = n_total;
    long long n_zero = n_total - n_copy;

    if (g_ready == 0) {
        // one-time resource creation (host-side objects only; happens on the
        // non-captured correctness call, never re-run during capture/replay)
        if (cudaStreamCreateWithFlags(&g_side, cudaStreamNonBlocking) == cudaSuccess &&
            cudaEventCreateWithFlags(&g_fork, cudaEventDisableTiming) == cudaSuccess &&
            cudaEventCreateWithFlags(&g_join, cudaEventDisableTiming) == cudaSuccess) {
            g_ready = 1;
        } else {
            g_ready = -1;
        }
    }

    if (g_ready == 1 && n_copy > 0 && n_zero > 0) {
        // fork: copy branch on side stream, memset on main (capture) stream
        cudaEventRecord(g_fork, 0);
        cudaStreamWaitEvent(g_side, g_fork, 0);

        cudaMemcpyAsync(out, hidden, (size_t)n_copy * sizeof(float),
                        cudaMemcpyDeviceToDevice, g_side);
        cudaEventRecord(g_join, g_side);

        cudaMemsetAsync(out + n_copy, 0, (size_t)n_zero * sizeof(float), 0);

        // join: main stream waits for the copy branch
        cudaStreamWaitEvent(0, g_join, 0);
    } else {
        // serial fallback (proven R3 path)
        if (n_copy > 0) {
            cudaMemcpyAsync(out, hidden, (size_t)n_copy * sizeof(float),
                            cudaMemcpyDeviceToDevice, 0);
        }
        if (n_zero > 0) {
            cudaMemsetAsync(out + n_copy, 0, (size_t)n_zero * sizeof(float), 0);
        }
    }
}